// round 1
// baseline (speedup 1.0000x reference)
#include <cuda_runtime.h>
#include <cuda_bf16.h>
#include <math.h>

// Problem constants
#define NB   96   // nodes
#define DD   64   // feature dim
#define BS   16   // batch
#define TT   13   // sequence length (12 steps)

// Scratch state (allocation-free rule: __device__ globals)
__device__ float g_hidden[BS * NB * DD];
__device__ float g_S[BS * NB * DD];      // sender-part:   hidden @ W_msg1[0:64]
__device__ float g_R[BS * NB * DD];      // receiver-part: hidden @ W_msg1[64:128]
__device__ float g_agg[BS * NB * DD];

__device__ __forceinline__ float tanh_fast(float x) {
    float y;
    asm("tanh.approx.f32 %0, %1;" : "=f"(y) : "f"(x));
    return y;
}

__device__ __forceinline__ float sigmoid_acc(float x) {
    return 1.0f / (1.0f + expf(-x));
}

// ---------------------------------------------------------------------------
// Init: zero hidden / S / R
// ---------------------------------------------------------------------------
__global__ void kInit() {
    int idx = blockIdx.x * blockDim.x + threadIdx.x;
    if (idx < BS * NB * DD) {
        g_hidden[idx] = 0.0f;
        g_S[idx] = 0.0f;
        g_R[idx] = 0.0f;
    }
}

// ---------------------------------------------------------------------------
// Kernel B (heavy): per (b,i) block:
//   T[j,k]  = tanh(S[b,j,k] + R[b,i,k] + bm1[k])           (96x64)
//   M       = T @ W_msg2 + b2                               (96x64 GEMM)
//   msg     = tanh(M)
//   agg[b,i,d] = (1/96) * sum_j adj[b,i,j] * msg[j,d]
// grid = 1536 blocks (b*96+i), 256 threads
// ---------------------------------------------------------------------------
__global__ void __launch_bounds__(256) kB(
    const float* __restrict__ adj,     // (1,16,96,96)
    const float* __restrict__ W2,      // (64,64) row-major [k][d]
    const float* __restrict__ bm1,     // (64)
    const float* __restrict__ b2)      // (64)
{
    __shared__ __align__(16) float sT[NB][DD + 1];   // padded: kills same-bank conflicts
    __shared__ __align__(16) float sW2[DD * DD];
    __shared__ float sAdj[NB];
    __shared__ float sRv[DD];
    __shared__ float sB2[DD];
    __shared__ __align__(16) float sRed[16 * DD];

    const int bx  = blockIdx.x;
    const int b   = bx / NB;
    const int i   = bx % NB;
    const int tid = threadIdx.x;

    // stage W2 (coalesced), receiver vector (+bias), adj row, b2
    for (int idx = tid; idx < DD * DD; idx += 256) sW2[idx] = W2[idx];
    if (tid < DD) {
        sRv[tid] = g_R[(b * NB + i) * DD + tid] + bm1[tid];
        sB2[tid] = b2[tid];
    }
    if (tid < NB) sAdj[tid] = adj[(b * NB + i) * NB + tid];
    __syncthreads();

    // build T = tanh(S[b,j,:] + rv)
    const float* Sb = &g_S[b * NB * DD];
    for (int idx = tid; idx < NB * DD; idx += 256) {
        int j = idx >> 6;
        int k = idx & 63;
        sT[j][k] = tanh_fast(Sb[idx] + sRv[k]);
    }
    __syncthreads();

    // register-blocked GEMM: thread owns 6 j's x 4 d's
    const int dgrp = tid & 15;       // 0..15 -> d0 = dgrp*4
    const int jgrp = tid >> 4;       // 0..15 -> j0 = jgrp*6
    const int d0   = dgrp * 4;
    const int j0   = jgrp * 6;

    float acc[6][4];
#pragma unroll
    for (int a = 0; a < 6; a++)
#pragma unroll
        for (int c = 0; c < 4; c++) acc[a][c] = 0.0f;

#pragma unroll 8
    for (int k = 0; k < DD; k++) {
        float4 w = *reinterpret_cast<const float4*>(&sW2[k * DD + d0]);
#pragma unroll
        for (int a = 0; a < 6; a++) {
            float tv = sT[j0 + a][k];
            acc[a][0] = fmaf(tv, w.x, acc[a][0]);
            acc[a][1] = fmaf(tv, w.y, acc[a][1]);
            acc[a][2] = fmaf(tv, w.z, acc[a][2]);
            acc[a][3] = fmaf(tv, w.w, acc[a][3]);
        }
    }

    // epilogue: msg = tanh(M + b2), weighted sum over this thread's 6 j's
    float bb0 = sB2[d0 + 0], bb1 = sB2[d0 + 1], bb2 = sB2[d0 + 2], bb3 = sB2[d0 + 3];
    float ws0 = 0.f, ws1 = 0.f, ws2 = 0.f, ws3 = 0.f;
#pragma unroll
    for (int a = 0; a < 6; a++) {
        float aj = sAdj[j0 + a];
        ws0 = fmaf(aj, tanh_fast(acc[a][0] + bb0), ws0);
        ws1 = fmaf(aj, tanh_fast(acc[a][1] + bb1), ws1);
        ws2 = fmaf(aj, tanh_fast(acc[a][2] + bb2), ws2);
        ws3 = fmaf(aj, tanh_fast(acc[a][3] + bb3), ws3);
    }
    *reinterpret_cast<float4*>(&sRed[jgrp * DD + d0]) = make_float4(ws0, ws1, ws2, ws3);
    __syncthreads();

    // final reduction over 16 j-groups -> agg
    if (tid < DD) {
        float s = 0.0f;
#pragma unroll
        for (int g = 0; g < 16; g++) s += sRed[g * DD + tid];
        g_agg[(b * NB + i) * DD + tid] = s * (1.0f / 96.0f);
    }
}

// ---------------------------------------------------------------------------
// Kernel C (light): GRU update + 3-layer prediction head + next-step S/R.
// grid = 64 blocks: b = bx>>2, rows n0 = (bx&3)*24, 256 threads = (4 rowgrp x 64 d)
// ---------------------------------------------------------------------------
__global__ void __launch_bounds__(256) kC(
    int t,
    const int*   __restrict__ skill_seq,  // (16,13)
    const float* __restrict__ emb,        // (1,96,64)
    const float* __restrict__ W_hr, const float* __restrict__ W_hi,
    const float* __restrict__ W_hh,
    const float* __restrict__ W_ir, const float* __restrict__ b_ir,
    const float* __restrict__ W_ii, const float* __restrict__ b_ii,
    const float* __restrict__ W_in, const float* __restrict__ b_in,
    const float* __restrict__ W_o1, const float* __restrict__ b_o1,
    const float* __restrict__ W_o2, const float* __restrict__ b_o2,
    const float* __restrict__ W_o3, const float* __restrict__ b_o3,
    const float* __restrict__ W_msg1,     // (128,64)
    float* __restrict__ out)              // (1,16,12,96,64)
{
    __shared__ float sA[24 * DD];
    __shared__ float sH[24 * DD];
    __shared__ float sHN[24 * DD];
    __shared__ float sP[24 * DD];
    __shared__ float sX[3 * DD];          // xr, xi, xn (bias included)
    __shared__ float sEmb[DD];

    const int bx  = blockIdx.x;
    const int b   = bx >> 2;
    const int n0  = (bx & 3) * 24;
    const int tid = threadIdx.x;
    const int d   = tid & 63;
    const int rg  = tid >> 6;             // 0..3 (6 rows each)

    // stage agg + hidden rows, embedding row
    const int base = (b * NB + n0) * DD;
    for (int idx = tid; idx < 24 * DD; idx += 256) {
        sA[idx] = g_agg[base + idx];
        sH[idx] = g_hidden[base + idx];
    }
    if (tid < DD) {
        int skill = skill_seq[b * TT + t];
        sEmb[tid] = emb[skill * DD + tid];
    }
    __syncthreads();

    // per-batch input projections: xr = emb@W_ir + b_ir, etc.
    if (rg < 3) {
        const float* W  = (rg == 0) ? W_ir : (rg == 1) ? W_ii : W_in;
        const float* bb = (rg == 0) ? b_ir : (rg == 1) ? b_ii : b_in;
        float a = bb[d];
#pragma unroll 8
        for (int k = 0; k < DD; k++) a = fmaf(sEmb[k], W[k * DD + d], a);
        sX[rg * DD + d] = a;
    }
    __syncthreads();

    // GRU gates per row: hr/hi/hh = agg @ W_h*
    float ahr[6], ahi[6], ahh[6];
#pragma unroll
    for (int r = 0; r < 6; r++) { ahr[r] = 0.f; ahi[r] = 0.f; ahh[r] = 0.f; }
#pragma unroll 4
    for (int k = 0; k < DD; k++) {
        float whr = W_hr[k * DD + d];
        float whi = W_hi[k * DD + d];
        float whh = W_hh[k * DD + d];
#pragma unroll
        for (int r = 0; r < 6; r++) {
            float av = sA[(rg * 6 + r) * DD + k];
            ahr[r] = fmaf(av, whr, ahr[r]);
            ahi[r] = fmaf(av, whi, ahi[r]);
            ahh[r] = fmaf(av, whh, ahh[r]);
        }
    }
    float xr = sX[d], xi = sX[DD + d], xn = sX[2 * DD + d];
#pragma unroll
    for (int r = 0; r < 6; r++) {
        int row = rg * 6 + r;
        float rr = sigmoid_acc(xr + ahr[r]);
        float ii = sigmoid_acc(xi + ahi[r]);
        float nn = tanhf(xn + rr * ahh[r]);
        float h  = sH[row * DD + d];
        float hn = (1.0f - ii) * nn + ii * h;
        sHN[row * DD + d] = hn;
        g_hidden[base + row * DD + d] = hn;
    }
    __syncthreads();

    // phase: pred layer1 + S + R (all read sHN)
    float ap[6], aS[6], aR[6];
#pragma unroll
    for (int r = 0; r < 6; r++) { ap[r] = 0.f; aS[r] = 0.f; aR[r] = 0.f; }
#pragma unroll 4
    for (int k = 0; k < DD; k++) {
        float w1 = W_o1[k * DD + d];
        float wS = W_msg1[k * DD + d];
        float wR = W_msg1[(DD + k) * DD + d];
#pragma unroll
        for (int r = 0; r < 6; r++) {
            float hv = sHN[(rg * 6 + r) * DD + k];
            ap[r] = fmaf(hv, w1, ap[r]);
            aS[r] = fmaf(hv, wS, aS[r]);
            aR[r] = fmaf(hv, wR, aR[r]);
        }
    }
    float bo1 = b_o1[d];
#pragma unroll
    for (int r = 0; r < 6; r++) {
        int row = rg * 6 + r;
        sP[row * DD + d] = fmaxf(ap[r] + bo1, 0.0f);
        g_S[base + row * DD + d] = aS[r];
        g_R[base + row * DD + d] = aR[r];
    }
    __syncthreads();

    // phase: pred layer2 (sP -> sA reused)
#pragma unroll
    for (int r = 0; r < 6; r++) ap[r] = 0.f;
#pragma unroll 4
    for (int k = 0; k < DD; k++) {
        float w2 = W_o2[k * DD + d];
#pragma unroll
        for (int r = 0; r < 6; r++)
            ap[r] = fmaf(sP[(rg * 6 + r) * DD + k], w2, ap[r]);
    }
    float bo2 = b_o2[d];
#pragma unroll
    for (int r = 0; r < 6; r++)
        sA[(rg * 6 + r) * DD + d] = fmaxf(ap[r] + bo2, 0.0f);
    __syncthreads();

    // phase: pred layer3 -> output (G,bs,12,N,D)
#pragma unroll
    for (int r = 0; r < 6; r++) ap[r] = 0.f;
#pragma unroll 4
    for (int k = 0; k < DD; k++) {
        float w3 = W_o3[k * DD + d];
#pragma unroll
        for (int r = 0; r < 6; r++)
            ap[r] = fmaf(sA[(rg * 6 + r) * DD + k], w3, ap[r]);
    }
    float bo3 = b_o3[d];
#pragma unroll
    for (int r = 0; r < 6; r++) {
        int row = rg * 6 + r;
        out[(((size_t)b * 12 + t) * NB + (n0 + row)) * DD + d] = ap[r] + bo3;
    }
}

// ---------------------------------------------------------------------------
extern "C" void kernel_launch(void* const* d_in, const int* in_sizes, int n_in,
                              void* d_out, int out_size) {
    const int*   skill_seq = (const int*)  d_in[0];
    const float* adj       = (const float*)d_in[1];
    const float* node_emb  = (const float*)d_in[2];
    const float* W_msg1    = (const float*)d_in[3];
    const float* b_msg1    = (const float*)d_in[4];
    const float* W_msg2    = (const float*)d_in[5];
    const float* b_msg2    = (const float*)d_in[6];
    const float* W_hr      = (const float*)d_in[7];
    const float* W_hi      = (const float*)d_in[8];
    const float* W_hh      = (const float*)d_in[9];
    const float* W_ir      = (const float*)d_in[10];
    const float* b_ir      = (const float*)d_in[11];
    const float* W_ii      = (const float*)d_in[12];
    const float* b_ii      = (const float*)d_in[13];
    const float* W_in      = (const float*)d_in[14];
    const float* b_in      = (const float*)d_in[15];
    const float* W_o1      = (const float*)d_in[16];
    const float* b_o1      = (const float*)d_in[17];
    const float* W_o2      = (const float*)d_in[18];
    const float* b_o2      = (const float*)d_in[19];
    const float* W_o3      = (const float*)d_in[20];
    const float* b_o3      = (const float*)d_in[21];
    float* out = (float*)d_out;

    kInit<<<(BS * NB * DD + 255) / 256, 256>>>();

    for (int t = 0; t < TT - 1; t++) {
        kB<<<BS * NB, 256>>>(adj, W_msg2, b_msg1, b_msg2);
        kC<<<64, 256>>>(t, skill_seq, node_emb,
                        W_hr, W_hi, W_hh,
                        W_ir, b_ir, W_ii, b_ii, W_in, b_in,
                        W_o1, b_o1, W_o2, b_o2, W_o3, b_o3,
                        W_msg1, out);
    }
}

// round 2
// speedup vs baseline: 1.0028x; 1.0028x over previous
#include <cuda_runtime.h>
#include <cuda_bf16.h>
#include <math.h>

// Problem constants
#define NB   96   // nodes
#define DD   64   // feature dim
#define BS   16   // batch
#define TT   13   // sequence length (12 steps)

// Scratch state (allocation-free rule: __device__ globals)
__device__ float g_hidden[BS * NB * DD];
__device__ float g_S[BS * NB * DD];      // sender-part:   hidden @ W_msg1[0:64]
__device__ float g_R[BS * NB * DD];      // receiver-part: hidden @ W_msg1[64:128]
__device__ float g_agg[BS * NB * DD];

__device__ __forceinline__ float tanh_fast(float x) {
    float y;
    asm("tanh.approx.f32 %0, %1;" : "=f"(y) : "f"(x));
    return y;
}

__device__ __forceinline__ float sigmoid_acc(float x) {
    return 1.0f / (1.0f + expf(-x));
}

// ---------------------------------------------------------------------------
// Init: zero hidden / S / R
// ---------------------------------------------------------------------------
__global__ void kInit() {
    int idx = blockIdx.x * blockDim.x + threadIdx.x;
    if (idx < BS * NB * DD) {
        g_hidden[idx] = 0.0f;
        g_S[idx] = 0.0f;
        g_R[idx] = 0.0f;
    }
}

// ---------------------------------------------------------------------------
// Kernel B (heavy): per (b,i) block:
//   T[j,k]  = tanh(S[b,j,k] + R[b,i,k] + bm1[k])           (96x64)
//   M       = T @ W_msg2 + b2                               (96x64 GEMM)
//   msg     = tanh(M)
//   agg[b,i,d] = (1/96) * sum_j adj[b,i,j] * msg[j,d]
// grid = 1536 blocks (b*96+i), 256 threads
// ---------------------------------------------------------------------------
__global__ void __launch_bounds__(256) kB(
    const float* __restrict__ adj,     // (1,16,96,96)
    const float* __restrict__ W2,      // (64,64) row-major [k][d]
    const float* __restrict__ bm1,     // (64)
    const float* __restrict__ b2)      // (64)
{
    __shared__ __align__(16) float sT[NB][DD + 1];   // padded: kills same-bank conflicts
    __shared__ __align__(16) float sW2[DD * DD];
    __shared__ float sAdj[NB];
    __shared__ float sRv[DD];
    __shared__ float sB2[DD];
    __shared__ __align__(16) float sRed[16 * DD];

    const int bx  = blockIdx.x;
    const int b   = bx / NB;
    const int i   = bx % NB;
    const int tid = threadIdx.x;

    // stage W2 (coalesced), receiver vector (+bias), adj row, b2
    for (int idx = tid; idx < DD * DD; idx += 256) sW2[idx] = W2[idx];
    if (tid < DD) {
        sRv[tid] = g_R[(b * NB + i) * DD + tid] + bm1[tid];
        sB2[tid] = b2[tid];
    }
    if (tid < NB) sAdj[tid] = adj[(b * NB + i) * NB + tid];
    __syncthreads();

    // build T = tanh(S[b,j,:] + rv)
    const float* Sb = &g_S[b * NB * DD];
    for (int idx = tid; idx < NB * DD; idx += 256) {
        int j = idx >> 6;
        int k = idx & 63;
        sT[j][k] = tanh_fast(Sb[idx] + sRv[k]);
    }
    __syncthreads();

    // register-blocked GEMM: thread owns 6 j's x 4 d's
    const int dgrp = tid & 15;       // 0..15 -> d0 = dgrp*4
    const int jgrp = tid >> 4;       // 0..15 -> j0 = jgrp*6
    const int d0   = dgrp * 4;
    const int j0   = jgrp * 6;

    float acc[6][4];
#pragma unroll
    for (int a = 0; a < 6; a++)
#pragma unroll
        for (int c = 0; c < 4; c++) acc[a][c] = 0.0f;

#pragma unroll 8
    for (int k = 0; k < DD; k++) {
        float4 w = *reinterpret_cast<const float4*>(&sW2[k * DD + d0]);
#pragma unroll
        for (int a = 0; a < 6; a++) {
            float tv = sT[j0 + a][k];
            acc[a][0] = fmaf(tv, w.x, acc[a][0]);
            acc[a][1] = fmaf(tv, w.y, acc[a][1]);
            acc[a][2] = fmaf(tv, w.z, acc[a][2]);
            acc[a][3] = fmaf(tv, w.w, acc[a][3]);
        }
    }

    // epilogue: msg = tanh(M + b2), weighted sum over this thread's 6 j's
    float bb0 = sB2[d0 + 0], bb1 = sB2[d0 + 1], bb2 = sB2[d0 + 2], bb3 = sB2[d0 + 3];
    float ws0 = 0.f, ws1 = 0.f, ws2 = 0.f, ws3 = 0.f;
#pragma unroll
    for (int a = 0; a < 6; a++) {
        float aj = sAdj[j0 + a];
        ws0 = fmaf(aj, tanh_fast(acc[a][0] + bb0), ws0);
        ws1 = fmaf(aj, tanh_fast(acc[a][1] + bb1), ws1);
        ws2 = fmaf(aj, tanh_fast(acc[a][2] + bb2), ws2);
        ws3 = fmaf(aj, tanh_fast(acc[a][3] + bb3), ws3);
    }
    *reinterpret_cast<float4*>(&sRed[jgrp * DD + d0]) = make_float4(ws0, ws1, ws2, ws3);
    __syncthreads();

    // final reduction over 16 j-groups -> agg
    if (tid < DD) {
        float s = 0.0f;
#pragma unroll
        for (int g = 0; g < 16; g++) s += sRed[g * DD + tid];
        g_agg[(b * NB + i) * DD + tid] = s * (1.0f / 96.0f);
    }
}

// ---------------------------------------------------------------------------
// Kernel C (light): GRU update + 3-layer prediction head + next-step S/R.
// grid = 64 blocks: b = bx>>2, rows n0 = (bx&3)*24, 256 threads = (4 rowgrp x 64 d)
// ---------------------------------------------------------------------------
__global__ void __launch_bounds__(256) kC(
    int t,
    const int*   __restrict__ skill_seq,  // (16,13)
    const float* __restrict__ emb,        // (1,96,64)
    const float* __restrict__ W_hr, const float* __restrict__ W_hi,
    const float* __restrict__ W_hh,
    const float* __restrict__ W_ir, const float* __restrict__ b_ir,
    const float* __restrict__ W_ii, const float* __restrict__ b_ii,
    const float* __restrict__ W_in, const float* __restrict__ b_in,
    const float* __restrict__ W_o1, const float* __restrict__ b_o1,
    const float* __restrict__ W_o2, const float* __restrict__ b_o2,
    const float* __restrict__ W_o3, const float* __restrict__ b_o3,
    const float* __restrict__ W_msg1,     // (128,64)
    float* __restrict__ out)              // (1,16,12,96,64)
{
    __shared__ float sA[24 * DD];
    __shared__ float sH[24 * DD];
    __shared__ float sHN[24 * DD];
    __shared__ float sP[24 * DD];
    __shared__ float sX[3 * DD];          // xr, xi, xn (bias included)
    __shared__ float sEmb[DD];

    const int bx  = blockIdx.x;
    const int b   = bx >> 2;
    const int n0  = (bx & 3) * 24;
    const int tid = threadIdx.x;
    const int d   = tid & 63;
    const int rg  = tid >> 6;             // 0..3 (6 rows each)

    // stage agg + hidden rows, embedding row
    const int base = (b * NB + n0) * DD;
    for (int idx = tid; idx < 24 * DD; idx += 256) {
        sA[idx] = g_agg[base + idx];
        sH[idx] = g_hidden[base + idx];
    }
    if (tid < DD) {
        int skill = skill_seq[b * TT + t];
        sEmb[tid] = emb[skill * DD + tid];
    }
    __syncthreads();

    // per-batch input projections: xr = emb@W_ir + b_ir, etc.
    if (rg < 3) {
        const float* W  = (rg == 0) ? W_ir : (rg == 1) ? W_ii : W_in;
        const float* bb = (rg == 0) ? b_ir : (rg == 1) ? b_ii : b_in;
        float a = bb[d];
#pragma unroll 8
        for (int k = 0; k < DD; k++) a = fmaf(sEmb[k], W[k * DD + d], a);
        sX[rg * DD + d] = a;
    }
    __syncthreads();

    // GRU gates per row: hr/hi/hh = agg @ W_h*
    float ahr[6], ahi[6], ahh[6];
#pragma unroll
    for (int r = 0; r < 6; r++) { ahr[r] = 0.f; ahi[r] = 0.f; ahh[r] = 0.f; }
#pragma unroll 4
    for (int k = 0; k < DD; k++) {
        float whr = W_hr[k * DD + d];
        float whi = W_hi[k * DD + d];
        float whh = W_hh[k * DD + d];
#pragma unroll
        for (int r = 0; r < 6; r++) {
            float av = sA[(rg * 6 + r) * DD + k];
            ahr[r] = fmaf(av, whr, ahr[r]);
            ahi[r] = fmaf(av, whi, ahi[r]);
            ahh[r] = fmaf(av, whh, ahh[r]);
        }
    }
    float xr = sX[d], xi = sX[DD + d], xn = sX[2 * DD + d];
#pragma unroll
    for (int r = 0; r < 6; r++) {
        int row = rg * 6 + r;
        float rr = sigmoid_acc(xr + ahr[r]);
        float ii = sigmoid_acc(xi + ahi[r]);
        float nn = tanhf(xn + rr * ahh[r]);
        float h  = sH[row * DD + d];
        float hn = (1.0f - ii) * nn + ii * h;
        sHN[row * DD + d] = hn;
        g_hidden[base + row * DD + d] = hn;
    }
    __syncthreads();

    // phase: pred layer1 + S + R (all read sHN)
    float ap[6], aS[6], aR[6];
#pragma unroll
    for (int r = 0; r < 6; r++) { ap[r] = 0.f; aS[r] = 0.f; aR[r] = 0.f; }
#pragma unroll 4
    for (int k = 0; k < DD; k++) {
        float w1 = W_o1[k * DD + d];
        float wS = W_msg1[k * DD + d];
        float wR = W_msg1[(DD + k) * DD + d];
#pragma unroll
        for (int r = 0; r < 6; r++) {
            float hv = sHN[(rg * 6 + r) * DD + k];
            ap[r] = fmaf(hv, w1, ap[r]);
            aS[r] = fmaf(hv, wS, aS[r]);
            aR[r] = fmaf(hv, wR, aR[r]);
        }
    }
    float bo1 = b_o1[d];
#pragma unroll
    for (int r = 0; r < 6; r++) {
        int row = rg * 6 + r;
        sP[row * DD + d] = fmaxf(ap[r] + bo1, 0.0f);
        g_S[base + row * DD + d] = aS[r];
        g_R[base + row * DD + d] = aR[r];
    }
    __syncthreads();

    // phase: pred layer2 (sP -> sA reused)
#pragma unroll
    for (int r = 0; r < 6; r++) ap[r] = 0.f;
#pragma unroll 4
    for (int k = 0; k < DD; k++) {
        float w2 = W_o2[k * DD + d];
#pragma unroll
        for (int r = 0; r < 6; r++)
            ap[r] = fmaf(sP[(rg * 6 + r) * DD + k], w2, ap[r]);
    }
    float bo2 = b_o2[d];
#pragma unroll
    for (int r = 0; r < 6; r++)
        sA[(rg * 6 + r) * DD + d] = fmaxf(ap[r] + bo2, 0.0f);
    __syncthreads();

    // phase: pred layer3 -> output (G,bs,12,N,D)
#pragma unroll
    for (int r = 0; r < 6; r++) ap[r] = 0.f;
#pragma unroll 4
    for (int k = 0; k < DD; k++) {
        float w3 = W_o3[k * DD + d];
#pragma unroll
        for (int r = 0; r < 6; r++)
            ap[r] = fmaf(sA[(rg * 6 + r) * DD + k], w3, ap[r]);
    }
    float bo3 = b_o3[d];
#pragma unroll
    for (int r = 0; r < 6; r++) {
        int row = rg * 6 + r;
        out[(((size_t)b * 12 + t) * NB + (n0 + row)) * DD + d] = ap[r] + bo3;
    }
}

// ---------------------------------------------------------------------------
extern "C" void kernel_launch(void* const* d_in, const int* in_sizes, int n_in,
                              void* d_out, int out_size) {
    const int*   skill_seq = (const int*)  d_in[0];
    const float* adj       = (const float*)d_in[1];
    const float* node_emb  = (const float*)d_in[2];
    const float* W_msg1    = (const float*)d_in[3];
    const float* b_msg1    = (const float*)d_in[4];
    const float* W_msg2    = (const float*)d_in[5];
    const float* b_msg2    = (const float*)d_in[6];
    const float* W_hr      = (const float*)d_in[7];
    const float* W_hi      = (const float*)d_in[8];
    const float* W_hh      = (const float*)d_in[9];
    const float* W_ir      = (const float*)d_in[10];
    const float* b_ir      = (const float*)d_in[11];
    const float* W_ii      = (const float*)d_in[12];
    const float* b_ii      = (const float*)d_in[13];
    const float* W_in      = (const float*)d_in[14];
    const float* b_in      = (const float*)d_in[15];
    const float* W_o1      = (const float*)d_in[16];
    const float* b_o1      = (const float*)d_in[17];
    const float* W_o2      = (const float*)d_in[18];
    const float* b_o2      = (const float*)d_in[19];
    const float* W_o3      = (const float*)d_in[20];
    const float* b_o3      = (const float*)d_in[21];
    float* out = (float*)d_out;

    kInit<<<(BS * NB * DD + 255) / 256, 256>>>();

    for (int t = 0; t < TT - 1; t++) {
        kB<<<BS * NB, 256>>>(adj, W_msg2, b_msg1, b_msg2);
        kC<<<64, 256>>>(t, skill_seq, node_emb,
                        W_hr, W_hi, W_hh,
                        W_ir, b_ir, W_ii, b_ii, W_in, b_in,
                        W_o1, b_o1, W_o2, b_o2, W_o3, b_o3,
                        W_msg1, out);
    }
}

// round 4
// speedup vs baseline: 1.3367x; 1.3330x over previous
#include <cuda_runtime.h>
#include <cuda_bf16.h>
#include <math.h>
#include <stdint.h>

// Problem constants
#define NB   96   // nodes
#define DD   64   // feature dim
#define BS   16   // batch
#define TT   13   // sequence length (12 steps)

#define STU  36   // shared row stride in u32 (= 72 bf16 = 144 B): conflict-free ldmatrix

// Scratch state (allocation-free rule: __device__ globals)
__device__ float g_hidden[BS * NB * DD];
__device__ float g_S[BS * NB * DD];      // sender-part:   hidden @ W_msg1[0:64]
__device__ float g_R[BS * NB * DD];      // receiver-part: hidden @ W_msg1[64:128]
__device__ float g_agg[BS * NB * DD];

// W2^T split into bf16 hi/lo, packed 2 k's per u32: layout [d][kp], d=0..63, kp=0..31
__device__ uint32_t g_w2t_hi[2048];
__device__ uint32_t g_w2t_lo[2048];

__device__ __forceinline__ float tanh_fast(float x) {
    float y;
    asm("tanh.approx.f32 %0, %1;" : "=f"(y) : "f"(x));
    return y;
}
__device__ __forceinline__ float sigmoid_acc(float x) {
    return 1.0f / (1.0f + expf(-x));
}
__device__ __forceinline__ uint32_t smem_u32(const void* p) {
    uint32_t a;
    asm("{ .reg .u64 t; cvta.to.shared.u64 t, %1; cvt.u32.u64 %0, t; }" : "=r"(a) : "l"(p));
    return a;
}
__device__ __forceinline__ void ldm_x4(uint32_t a[4], uint32_t addr) {
    asm volatile("ldmatrix.sync.aligned.m8n8.x4.shared.b16 {%0,%1,%2,%3}, [%4];"
        : "=r"(a[0]), "=r"(a[1]), "=r"(a[2]), "=r"(a[3]) : "r"(addr));
}
__device__ __forceinline__ void ldm_x2(uint32_t& r0, uint32_t& r1, uint32_t addr) {
    asm volatile("ldmatrix.sync.aligned.m8n8.x2.shared.b16 {%0,%1}, [%2];"
        : "=r"(r0), "=r"(r1) : "r"(addr));
}
__device__ __forceinline__ void mma_bf16(float c[4], const uint32_t a[4],
                                         uint32_t b0, uint32_t b1) {
    asm volatile("mma.sync.aligned.m16n8k16.row.col.f32.bf16.bf16.f32 "
        "{%0,%1,%2,%3}, {%4,%5,%6,%7}, {%8,%9}, {%0,%1,%2,%3};"
        : "+f"(c[0]), "+f"(c[1]), "+f"(c[2]), "+f"(c[3])
        : "r"(a[0]), "r"(a[1]), "r"(a[2]), "r"(a[3]), "r"(b0), "r"(b1));
}
__device__ __forceinline__ uint32_t pack_bf16x2(float lo_val, float hi_val) {
    __nv_bfloat16 l = __float2bfloat16(lo_val);
    __nv_bfloat16 h = __float2bfloat16(hi_val);
    return ((uint32_t)__bfloat16_as_ushort(h) << 16) | __bfloat16_as_ushort(l);
}

// ---------------------------------------------------------------------------
__global__ void kInit() {
    int idx = blockIdx.x * blockDim.x + threadIdx.x;
    if (idx < BS * NB * DD) {
        g_hidden[idx] = 0.0f;
        g_S[idx] = 0.0f;
        g_R[idx] = 0.0f;
    }
}

// Prep (once): Wt[d][k] = W2[k][d], bf16 hi/lo split, 2 k's packed per u32.
__global__ void kPrep(const float* __restrict__ W2) {
    int tid = threadIdx.x;
    for (int idx = tid; idx < 2048; idx += 256) {
        int d  = idx >> 5;
        int kp = idx & 31;
        float w0 = W2[(2 * kp)     * DD + d];
        float w1 = W2[(2 * kp + 1) * DD + d];
        __nv_bfloat16 h0 = __float2bfloat16(w0);
        __nv_bfloat16 h1 = __float2bfloat16(w1);
        float l0 = w0 - __bfloat162float(h0);
        float l1 = w1 - __bfloat162float(h1);
        g_w2t_hi[idx] = ((uint32_t)__bfloat16_as_ushort(h1) << 16) | __bfloat16_as_ushort(h0);
        g_w2t_lo[idx] = pack_bf16x2(l0, l1);
    }
}

// ---------------------------------------------------------------------------
// Kernel B (heavy, HMMA mma.sync): per (b,i) CTA:
//   T[j,k]   = tanh(S[b,j,k] + R[b,i,k] + bm1[k])         (96x64, bf16 hi/lo)
//   C[j,d]   = sum_k T[j,k] * W2[k,d]    (3-pass bf16 split, m16n8k16 HMMA)
//   agg[b,i,d] = (1/96)*sum_j adj[b,i,j]*tanh(C[j,d]+b2[d])  (fragment epilogue)
// 256 threads = 8 warps: warp = (wm in 0..1 over m) x (wn in 0..3 over n).
// Warp owns 3 m-tiles (16j) x 2 n-tiles (8d).
// ---------------------------------------------------------------------------
__global__ void __launch_bounds__(256) kB(
    const float* __restrict__ adj,     // (1,16,96,96)
    const float* __restrict__ bm1,     // (64)
    const float* __restrict__ b2)      // (64)
{
    __shared__ uint32_t sThi[NB * STU];   // 13824 B
    __shared__ uint32_t sTlo[NB * STU];   // 13824 B
    __shared__ uint32_t sWhi[DD * STU];   //  9216 B
    __shared__ uint32_t sWlo[DD * STU];   //  9216 B
    __shared__ float sAdj[NB];
    __shared__ float sB2[DD];
    __shared__ float sRv[DD];
    __shared__ float sRed[2][DD];

    const int bx   = blockIdx.x;
    const int b    = bx / NB;
    const int i    = bx % NB;
    const int tid  = threadIdx.x;
    const int wid  = tid >> 5;
    const int lane = tid & 31;

    // stage W images + adj row + biases
    for (int idx = tid; idx < 2048; idx += 256) {
        int d = idx >> 5, kp = idx & 31;
        sWhi[d * STU + kp] = g_w2t_hi[idx];
        sWlo[d * STU + kp] = g_w2t_lo[idx];
    }
    if (tid < DD) {
        sRv[tid] = g_R[(b * NB + i) * DD + tid] + bm1[tid];
        sB2[tid] = b2[tid];
    }
    if (tid < NB) sAdj[tid] = adj[(b * NB + i) * NB + tid];
    __syncthreads();

    // build T = tanh(S[b,j,:] + rv) -> bf16 hi/lo (2 k's per u32)
    const float* Sb = &g_S[b * NB * DD];
#pragma unroll
    for (int p = 0; p < 12; p++) {
        int idx = tid + p * 256;          // 0..3071
        int j  = idx >> 5;
        int kp = idx & 31;
        float2 s = *reinterpret_cast<const float2*>(&Sb[j * DD + kp * 2]);
        float t0 = tanh_fast(s.x + sRv[kp * 2]);
        float t1 = tanh_fast(s.y + sRv[kp * 2 + 1]);
        __nv_bfloat16 h0 = __float2bfloat16(t0);
        __nv_bfloat16 h1 = __float2bfloat16(t1);
        sThi[j * STU + kp] = ((uint32_t)__bfloat16_as_ushort(h1) << 16) | __bfloat16_as_ushort(h0);
        sTlo[j * STU + kp] = pack_bf16x2(t0 - __bfloat162float(h0), t1 - __bfloat162float(h1));
    }
    __syncthreads();

    // ---- HMMA main: warp (wm, wn) ----
    const int wn = wid & 3;
    const int wm = wid >> 2;
    const int d0 = wn * 16;

    const uint32_t tThi = smem_u32(sThi);
    const uint32_t tTlo = smem_u32(sTlo);
    const uint32_t tWhi = smem_u32(sWhi);
    const uint32_t tWlo = smem_u32(sWlo);

    // ldmatrix lane->row mapping
    const int a_joff = (lane & 7) + ((lane & 8) ? 8 : 0);    // lane>>3 bit0 -> +8 rows
    const int a_koff = (lane & 16) ? 8 : 0;                  // lane>>3 bit1 -> +8 k
    const int bl     = lane & 15;
    const int b_nrow = bl & 7;
    const int b_koff = (bl & 8) ? 8 : 0;

    float c[3][2][4];
#pragma unroll
    for (int mt = 0; mt < 3; mt++)
#pragma unroll
        for (int nt = 0; nt < 2; nt++)
#pragma unroll
            for (int r = 0; r < 4; r++) c[mt][nt][r] = 0.0f;

#pragma unroll
    for (int pass = 0; pass < 3; pass++) {
        const uint32_t Ab = (pass == 1) ? tTlo : tThi;
        const uint32_t Bb = (pass == 2) ? tWlo : tWhi;
#pragma unroll
        for (int ks = 0; ks < 4; ks++) {
            const int k0 = ks * 16;
            uint32_t bf[2][2];
#pragma unroll
            for (int nt = 0; nt < 2; nt++) {
                uint32_t baddr = Bb + ((d0 + nt * 8 + b_nrow) * STU + ((k0 + b_koff) >> 1)) * 4;
                ldm_x2(bf[nt][0], bf[nt][1], baddr);
            }
#pragma unroll
            for (int mt = 0; mt < 3; mt++) {
                const int jm = (wm * 3 + mt) * 16;
                uint32_t af[4];
                uint32_t aaddr = Ab + ((jm + a_joff) * STU + ((k0 + a_koff) >> 1)) * 4;
                ldm_x4(af, aaddr);
                mma_bf16(c[mt][0], af, bf[0][0], bf[0][1]);
                mma_bf16(c[mt][1], af, bf[1][0], bf[1][1]);
            }
        }
    }

    // ---- epilogue: tanh + adj-weighted j-reduction in fragments ----
    const int g4 = lane >> 2;
    const int c4 = lane & 3;
    float acc[2][2] = {{0.f, 0.f}, {0.f, 0.f}};
    float b2v[2][2];
#pragma unroll
    for (int nt = 0; nt < 2; nt++) {
        b2v[nt][0] = sB2[d0 + nt * 8 + 2 * c4];
        b2v[nt][1] = sB2[d0 + nt * 8 + 2 * c4 + 1];
    }
#pragma unroll
    for (int mt = 0; mt < 3; mt++) {
        const int jb = (wm * 3 + mt) * 16;
        float aj0 = sAdj[jb + g4];
        float aj1 = sAdj[jb + 8 + g4];
#pragma unroll
        for (int nt = 0; nt < 2; nt++) {
            acc[nt][0] = fmaf(aj0, tanh_fast(c[mt][nt][0] + b2v[nt][0]), acc[nt][0]);
            acc[nt][1] = fmaf(aj0, tanh_fast(c[mt][nt][1] + b2v[nt][1]), acc[nt][1]);
            acc[nt][0] = fmaf(aj1, tanh_fast(c[mt][nt][2] + b2v[nt][0]), acc[nt][0]);
            acc[nt][1] = fmaf(aj1, tanh_fast(c[mt][nt][3] + b2v[nt][1]), acc[nt][1]);
        }
    }
    // reduce across g4 (lane bits 2..4)
#pragma unroll
    for (int off = 4; off <= 16; off <<= 1) {
#pragma unroll
        for (int nt = 0; nt < 2; nt++) {
#pragma unroll
            for (int cc = 0; cc < 2; cc++)
                acc[nt][cc] += __shfl_xor_sync(0xffffffffu, acc[nt][cc], off);
        }
    }
    if (lane < 4) {
        sRed[wm][d0 + 2 * lane]         = acc[0][0];
        sRed[wm][d0 + 2 * lane + 1]     = acc[0][1];
        sRed[wm][d0 + 8 + 2 * lane]     = acc[1][0];
        sRed[wm][d0 + 8 + 2 * lane + 1] = acc[1][1];
    }
    __syncthreads();
    if (tid < DD)
        g_agg[(b * NB + i) * DD + tid] = (sRed[0][tid] + sRed[1][tid]) * (1.0f / 96.0f);
}

// ---------------------------------------------------------------------------
// Kernel C (light): GRU update + 3-layer prediction head + next-step S/R.
// grid = 128 blocks: b = bx>>3, rows n0 = (bx&7)*12, 256 threads = 4 rowgrp x 64 d
// ---------------------------------------------------------------------------
#define RPB 12   // rows per block
#define RPG 3    // rows per rowgroup

__global__ void __launch_bounds__(256) kC(
    int t,
    const int*   __restrict__ skill_seq,  // (16,13)
    const float* __restrict__ emb,        // (1,96,64)
    const float* __restrict__ W_hr, const float* __restrict__ W_hi,
    const float* __restrict__ W_hh,
    const float* __restrict__ W_ir, const float* __restrict__ b_ir,
    const float* __restrict__ W_ii, const float* __restrict__ b_ii,
    const float* __restrict__ W_in, const float* __restrict__ b_in,
    const float* __restrict__ W_o1, const float* __restrict__ b_o1,
    const float* __restrict__ W_o2, const float* __restrict__ b_o2,
    const float* __restrict__ W_o3, const float* __restrict__ b_o3,
    const float* __restrict__ W_msg1,     // (128,64)
    float* __restrict__ out)              // (1,16,12,96,64)
{
    __shared__ float sA[RPB * DD];
    __shared__ float sH[RPB * DD];
    __shared__ float sHN[RPB * DD];
    __shared__ float sP[RPB * DD];
    __shared__ float sX[3 * DD];
    __shared__ float sEmb[DD];

    const int bx  = blockIdx.x;
    const int b   = bx >> 3;
    const int n0  = (bx & 7) * RPB;
    const int tid = threadIdx.x;
    const int d   = tid & 63;
    const int rg  = tid >> 6;

    const int base = (b * NB + n0) * DD;
    for (int idx = tid; idx < RPB * DD; idx += 256) {
        sA[idx] = g_agg[base + idx];
        sH[idx] = g_hidden[base + idx];
    }
    if (tid < DD) {
        int skill = skill_seq[b * TT + t];
        sEmb[tid] = emb[skill * DD + tid];
    }
    __syncthreads();

    if (rg < 3) {
        const float* W  = (rg == 0) ? W_ir : (rg == 1) ? W_ii : W_in;
        const float* bb = (rg == 0) ? b_ir : (rg == 1) ? b_ii : b_in;
        float a = bb[d];
#pragma unroll 8
        for (int k = 0; k < DD; k++) a = fmaf(sEmb[k], W[k * DD + d], a);
        sX[rg * DD + d] = a;
    }
    __syncthreads();

    float ahr[RPG], ahi[RPG], ahh[RPG];
#pragma unroll
    for (int r = 0; r < RPG; r++) { ahr[r] = 0.f; ahi[r] = 0.f; ahh[r] = 0.f; }
#pragma unroll 4
    for (int k = 0; k < DD; k++) {
        float whr = W_hr[k * DD + d];
        float whi = W_hi[k * DD + d];
        float whh = W_hh[k * DD + d];
#pragma unroll
        for (int r = 0; r < RPG; r++) {
            float av = sA[(rg * RPG + r) * DD + k];
            ahr[r] = fmaf(av, whr, ahr[r]);
            ahi[r] = fmaf(av, whi, ahi[r]);
            ahh[r] = fmaf(av, whh, ahh[r]);
        }
    }
    float xr = sX[d], xi = sX[DD + d], xn = sX[2 * DD + d];
#pragma unroll
    for (int r = 0; r < RPG; r++) {
        int row = rg * RPG + r;
        float rr = sigmoid_acc(xr + ahr[r]);
        float ii = sigmoid_acc(xi + ahi[r]);
        float nn = tanhf(xn + rr * ahh[r]);
        float h  = sH[row * DD + d];
        float hn = (1.0f - ii) * nn + ii * h;
        sHN[row * DD + d] = hn;
        g_hidden[base + row * DD + d] = hn;
    }
    __syncthreads();

    float ap[RPG], aS[RPG], aR[RPG];
#pragma unroll
    for (int r = 0; r < RPG; r++) { ap[r] = 0.f; aS[r] = 0.f; aR[r] = 0.f; }
#pragma unroll 4
    for (int k = 0; k < DD; k++) {
        float w1 = W_o1[k * DD + d];
        float wS = W_msg1[k * DD + d];
        float wR = W_msg1[(DD + k) * DD + d];
#pragma unroll
        for (int r = 0; r < RPG; r++) {
            float hv = sHN[(rg * RPG + r) * DD + k];
            ap[r] = fmaf(hv, w1, ap[r]);
            aS[r] = fmaf(hv, wS, aS[r]);
            aR[r] = fmaf(hv, wR, aR[r]);
        }
    }
    float bo1 = b_o1[d];
#pragma unroll
    for (int r = 0; r < RPG; r++) {
        int row = rg * RPG + r;
        sP[row * DD + d] = fmaxf(ap[r] + bo1, 0.0f);
        g_S[base + row * DD + d] = aS[r];
        g_R[base + row * DD + d] = aR[r];
    }
    __syncthreads();

#pragma unroll
    for (int r = 0; r < RPG; r++) ap[r] = 0.f;
#pragma unroll 4
    for (int k = 0; k < DD; k++) {
        float w2 = W_o2[k * DD + d];
#pragma unroll
        for (int r = 0; r < RPG; r++)
            ap[r] = fmaf(sP[(rg * RPG + r) * DD + k], w2, ap[r]);
    }
    float bo2 = b_o2[d];
#pragma unroll
    for (int r = 0; r < RPG; r++)
        sA[(rg * RPG + r) * DD + d] = fmaxf(ap[r] + bo2, 0.0f);
    __syncthreads();

#pragma unroll
    for (int r = 0; r < RPG; r++) ap[r] = 0.f;
#pragma unroll 4
    for (int k = 0; k < DD; k++) {
        float w3 = W_o3[k * DD + d];
#pragma unroll
        for (int r = 0; r < RPG; r++)
            ap[r] = fmaf(sA[(rg * RPG + r) * DD + k], w3, ap[r]);
    }
    float bo3 = b_o3[d];
#pragma unroll
    for (int r = 0; r < RPG; r++) {
        int row = rg * RPG + r;
        out[(((size_t)b * 12 + t) * NB + (n0 + row)) * DD + d] = ap[r] + bo3;
    }
}

// ---------------------------------------------------------------------------
extern "C" void kernel_launch(void* const* d_in, const int* in_sizes, int n_in,
                              void* d_out, int out_size) {
    const int*   skill_seq = (const int*)  d_in[0];
    const float* adj       = (const float*)d_in[1];
    const float* node_emb  = (const float*)d_in[2];
    const float* W_msg1    = (const float*)d_in[3];
    const float* b_msg1    = (const float*)d_in[4];
    const float* W_msg2    = (const float*)d_in[5];
    const float* b_msg2    = (const float*)d_in[6];
    const float* W_hr      = (const float*)d_in[7];
    const float* W_hi      = (const float*)d_in[8];
    const float* W_hh      = (const float*)d_in[9];
    const float* W_ir      = (const float*)d_in[10];
    const float* b_ir      = (const float*)d_in[11];
    const float* W_ii      = (const float*)d_in[12];
    const float* b_ii      = (const float*)d_in[13];
    const float* W_in      = (const float*)d_in[14];
    const float* b_in      = (const float*)d_in[15];
    const float* W_o1      = (const float*)d_in[16];
    const float* b_o1      = (const float*)d_in[17];
    const float* W_o2      = (const float*)d_in[18];
    const float* b_o2      = (const float*)d_in[19];
    const float* W_o3      = (const float*)d_in[20];
    const float* b_o3      = (const float*)d_in[21];
    float* out = (float*)d_out;

    kInit<<<(BS * NB * DD + 255) / 256, 256>>>();
    kPrep<<<1, 256>>>(W_msg2);

    for (int t = 0; t < TT - 1; t++) {
        kB<<<BS * NB, 256>>>(adj, b_msg1, b_msg2);
        kC<<<128, 256>>>(t, skill_seq, node_emb,
                         W_hr, W_hi, W_hh,
                         W_ir, b_ir, W_ii, b_ii, W_in, b_in,
                         W_o1, b_o1, W_o2, b_o2, W_o3, b_o3,
                         W_msg1, out);
    }
}